// round 1
// baseline (speedup 1.0000x reference)
#include <cuda_runtime.h>

#define CH 16
#define RES 512
#define PLANE_TEX (RES * RES)

// Channel-last transposed feature maps: fmt[plane][x][y][c], 48 MB scratch.
__device__ __align__(16) float g_fmt[3ull * PLANE_TEX * CH];

// ---------------------------------------------------------------------------
// Transpose (48,512,512) channel-major -> (3,512,512,16) channel-last.
// One thread per texel (p, x, y): 16 coalesced loads (adjacent lanes = adjacent
// y for each channel), 4x STG.128 writes covering a contiguous 2KB/warp region.
// ---------------------------------------------------------------------------
__global__ void __launch_bounds__(256) transpose_k(const float* __restrict__ fm) {
    int idx = blockIdx.x * 256 + threadIdx.x;          // 0 .. 3*PLANE_TEX-1 (exact multiple)
    int p  = idx >> 18;                                // / 262144
    int xy = idx & (PLANE_TEX - 1);

    float v[CH];
#pragma unroll
    for (int c = 0; c < CH; ++c)
        v[c] = __ldcs(fm + (size_t)(p * CH + c) * PLANE_TEX + xy);

    float4* dst = reinterpret_cast<float4*>(g_fmt + (size_t)idx * CH);
#pragma unroll
    for (int i = 0; i < 4; ++i)
        dst[i] = make_float4(v[4 * i], v[4 * i + 1], v[4 * i + 2], v[4 * i + 3]);
}

// ---------------------------------------------------------------------------
// Sampling: one thread per (point, plane). t = n*3 + pl, so the output slot is
// exactly out[t*16 .. t*16+15] (concat order f_xy, f_yz, f_zx == pl 0,1,2).
// 16 independent LDG.128 from L2-resident fmt, 4 streaming STG.128.
// ---------------------------------------------------------------------------
__global__ void __launch_bounds__(256) sample_k(const float* __restrict__ xyz,
                                                float* __restrict__ out, int total) {
    int t = blockIdx.x * 256 + threadIdx.x;
    if (t >= total) return;
    int n  = t / 3;
    int pl = t - n * 3;

    float X = __ldcs(xyz + 3 * n + 0);
    float Y = __ldcs(xyz + 3 * n + 1);
    float Z = __ldcs(xyz + 3 * n + 2);

    // pl 0: f_xy -> planes[0], coords (x, y),        scales (1, 1)
    // pl 1: f_yz -> planes[2], coords (y, z),        scales (1, SCALE_D)
    // pl 2: f_zx -> planes[1], coords (z, x),        scales (SCALE_D, 1)
    float c0, c1; int fp;
    if (pl == 0)      { c0 = X;           c1 = Y;           fp = 0; }
    else if (pl == 1) { c0 = Y;           c1 = Z / 0.05f;   fp = 2; }
    else              { c0 = Z / 0.05f;   c1 = X;           fp = 1; }

    // (c/s + 1) * (512-1) * 0.5  == (c/s + 1) * 255.5 (power-of-2 scaling, same rounding)
    float x = (c0 + 1.0f) * 255.5f;
    float y = (c1 + 1.0f) * 255.5f;

    float x0f = floorf(x), y0f = floorf(y);
    float fx = x - x0f;          // exact (Sterbenz)
    float fy = y - y0f;
    float gx = 1.0f - fx;        // == (x1 - x) correctly rounded, same as reference
    float gy = 1.0f - fy;

    float wa = gx * gy;          // (x0,y0)
    float wb = fx * gy;          // (x1,y0)
    float wc = gx * fy;          // (x0,y1)
    float wd = fx * fy;          // (x1,y1)

    int xi = min(max((int)x0f, 0), RES - 2);   // x1i == xi+1 in all clip cases
    int yi = min(max((int)y0f, 0), RES - 2);

    const float4* base = reinterpret_cast<const float4*>(g_fmt)
                         + ((size_t)fp * RES + xi) * (RES * 4) + (size_t)yi * 4;

    // Issue all 16 loads up front for MLP (L2 latency ~250 cyc).
    float4 A0 = base[0],           A1 = base[1],           A2 = base[2],           A3 = base[3];
    float4 C0 = base[4],           C1 = base[5],           C2 = base[6],           C3 = base[7];
    float4 B0 = base[RES * 4 + 0], B1 = base[RES * 4 + 1], B2 = base[RES * 4 + 2], B3 = base[RES * 4 + 3];
    float4 D0 = base[RES * 4 + 4], D1 = base[RES * 4 + 5], D2 = base[RES * 4 + 6], D3 = base[RES * 4 + 7];

    float4 r0, r1, r2, r3;
#define BLEND(r, A, B, C, D)                                            \
    r.x = wa * A.x + wb * B.x + wc * C.x + wd * D.x;                    \
    r.y = wa * A.y + wb * B.y + wc * C.y + wd * D.y;                    \
    r.z = wa * A.z + wb * B.z + wc * C.z + wd * D.z;                    \
    r.w = wa * A.w + wb * B.w + wc * C.w + wd * D.w;
    BLEND(r0, A0, B0, C0, D0)
    BLEND(r1, A1, B1, C1, D1)
    BLEND(r2, A2, B2, C2, D2)
    BLEND(r3, A3, B3, C3, D3)
#undef BLEND

    float4* o = reinterpret_cast<float4*>(out) + (size_t)t * 4;
    __stcs(o + 0, r0);
    __stcs(o + 1, r1);
    __stcs(o + 2, r2);
    __stcs(o + 3, r3);
}

extern "C" void kernel_launch(void* const* d_in, const int* in_sizes, int n_in,
                              void* d_out, int out_size) {
    const float* xyz = (const float*)d_in[0];        // (N, 3) float32
    const float* fm  = (const float*)d_in[1];        // (48, 512, 512) float32
    float* out = (float*)d_out;                      // (N, 48) float32
    int N = in_sizes[0] / 3;
    int total = N * 3;

    transpose_k<<<(3 * PLANE_TEX) / 256, 256>>>(fm);
    sample_k<<<(total + 255) / 256, 256>>>(xyz, out, total);
}

// round 2
// speedup vs baseline: 2.0546x; 2.0546x over previous
#include <cuda_runtime.h>

#define CH 16
#define RES 512
#define PLANE_TEX (RES * RES)

// Channel-last transposed feature maps: fmt[plane][x][y][c], 48 MB scratch.
__device__ __align__(16) float g_fmt[3ull * PLANE_TEX * CH];

// ---------------------------------------------------------------------------
// Transpose (48,512,512) channel-major -> (3,512,512,16) channel-last.
// ---------------------------------------------------------------------------
__global__ void __launch_bounds__(256) transpose_k(const float* __restrict__ fm) {
    int idx = blockIdx.x * 256 + threadIdx.x;          // 0 .. 3*PLANE_TEX-1
    int p  = idx >> 18;
    int xy = idx & (PLANE_TEX - 1);

    float v[CH];
#pragma unroll
    for (int c = 0; c < CH; ++c)
        v[c] = __ldcs(fm + (size_t)(p * CH + c) * PLANE_TEX + xy);

    float4* dst = reinterpret_cast<float4*>(g_fmt + (size_t)idx * CH);
#pragma unroll
    for (int i = 0; i < 4; ++i)
        dst[i] = make_float4(v[4 * i], v[4 * i + 1], v[4 * i + 2], v[4 * i + 3]);
}

// ---------------------------------------------------------------------------
// Sampling: FOUR threads per (point, plane); thread j handles channels 4j..4j+3.
// For each corner, the 4 lanes of a point-plane load consecutive float4s of a
// 64B-aligned texel block -> they coalesce into ONE 128B L1 wavefront.
// Per warp (8 point-planes): 4 corner LDG.128s ~= 8 wavefronts each = 32,
// vs 512 in the 1-thread-per-pp scheme. L1tex pressure drops ~4x.
// ---------------------------------------------------------------------------
__global__ void __launch_bounds__(256) sample_k(const float* __restrict__ xyz,
                                                float* __restrict__ out, int nPP) {
    int g  = blockIdx.x * 256 + threadIdx.x;
    int pp = g >> 2;              // point-plane index (t = n*3 + pl)
    int j  = g & 3;               // channel group 0..3
    if (pp >= nPP) return;
    int n  = pp / 3;
    int pl = pp - n * 3;

    float X = __ldg(xyz + 3 * n + 0);
    float Y = __ldg(xyz + 3 * n + 1);
    float Z = __ldg(xyz + 3 * n + 2);

    // pl 0: f_xy -> planes[0], (x, y)           scales (1, 1)
    // pl 1: f_yz -> planes[2], (y, z/0.05)      scales (1, SCALE_D)
    // pl 2: f_zx -> planes[1], (z/0.05, x)      scales (SCALE_D, 1)
    float c0, c1; int fp;
    if (pl == 0)      { c0 = X;         c1 = Y;         fp = 0; }
    else if (pl == 1) { c0 = Y;         c1 = Z / 0.05f; fp = 2; }
    else              { c0 = Z / 0.05f; c1 = X;         fp = 1; }

    // (c/s + 1) * 255.5 — identical rounding to reference's (c/s+1)*511*0.5
    float x = (c0 + 1.0f) * 255.5f;
    float y = (c1 + 1.0f) * 255.5f;

    float x0f = floorf(x), y0f = floorf(y);
    float fx = x - x0f;      // exact (Sterbenz)
    float fy = y - y0f;
    float gx = 1.0f - fx;    // matches reference (x1 - x)
    float gy = 1.0f - fy;

    float wa = gx * gy;      // (x0,y0)
    float wb = fx * gy;      // (x1,y0)
    float wc = gx * fy;      // (x0,y1)
    float wd = fx * fy;      // (x1,y1)

    int xi = min(max((int)x0f, 0), RES - 2);   // x1i == xi+1 in all clip cases
    int yi = min(max((int)y0f, 0), RES - 2);

    const float4* base = reinterpret_cast<const float4*>(g_fmt)
                         + ((size_t)fp * RES + xi) * (RES * 4) + (size_t)yi * 4 + j;

    // 4 independent corner loads, issued up front for MLP.
    float4 A = base[0];            // (xi,   yi)
    float4 C = base[4];            // (xi,   yi+1)
    float4 B = base[RES * 4];      // (xi+1, yi)
    float4 D = base[RES * 4 + 4];  // (xi+1, yi+1)

    float4 r;
    r.x = wa * A.x + wb * B.x + wc * C.x + wd * D.x;
    r.y = wa * A.y + wb * B.y + wc * C.y + wd * D.y;
    r.z = wa * A.z + wb * B.z + wc * C.z + wd * D.z;
    r.w = wa * A.w + wb * B.w + wc * C.w + wd * D.w;

    __stcs(reinterpret_cast<float4*>(out) + (size_t)pp * 4 + j, r);
}

extern "C" void kernel_launch(void* const* d_in, const int* in_sizes, int n_in,
                              void* d_out, int out_size) {
    const float* xyz = (const float*)d_in[0];        // (N, 3) float32
    const float* fm  = (const float*)d_in[1];        // (48, 512, 512) float32
    float* out = (float*)d_out;                      // (N, 48) float32
    int N = in_sizes[0] / 3;
    int nPP = N * 3;
    long long threads = (long long)nPP * 4;
    int blocks = (int)((threads + 255) / 256);

    transpose_k<<<(3 * PLANE_TEX) / 256, 256>>>(fm);
    sample_k<<<blocks, 256>>>(xyz, out, nPP);
}

// round 3
// speedup vs baseline: 2.1253x; 1.0344x over previous
#include <cuda_runtime.h>
#include <cuda_fp16.h>

#define CH 16
#define RES 512
#define PLANE_TEX (RES * RES)

// Packed, y-pair-interleaved, fp16, two shifted copies:
//   g_pack[copy(2)][plane(3)][x(512)][Y(256)][ch(16)][dy(2)]  (__half)
// copy 0: Y-block holds rows (2Y, 2Y+1); copy 1: (2Y+1, 2Y+2).
// One 64B block per (x, y-pair) -> a sample's row fetch is ONE aligned line.
__device__ __align__(16) __half g_pack[2u * 3 * 512 * 256 * 32];

#define COPY_STRIDE (3 * 512 * 256 * 32)   // halves per copy
#define ROW_STRIDE  (256 * 32)             // halves per x-row

// ---------------------------------------------------------------------------
// Pack kernel: one thread per (plane, x, Y). Reads y = 2Y, 2Y+1, 2Y+2 for all
// 16 channels, writes both copies' blocks (half2 per channel = (y0, y1)).
// ---------------------------------------------------------------------------
__global__ void __launch_bounds__(256) pack_k(const float* __restrict__ fm) {
    int idx = blockIdx.x * 256 + threadIdx.x;   // 0 .. 3*512*256-1
    int Y  = idx & 255;
    int px = idx >> 8;                          // p*512 + x
    int p  = px >> 9;
    int x  = px & 511;

    const float* src = fm + (size_t)p * (CH * PLANE_TEX) + (size_t)x * RES + 2 * Y;

    union Blk { __half2 h[16]; uint4 u[4]; };
    Blk b0, b1;
#pragma unroll
    for (int c = 0; c < CH; ++c) {
        const float* s = src + (size_t)c * PLANE_TEX;
        float f0 = __ldcs(s);
        float f1 = __ldcs(s + 1);
        float f2 = (Y < 255) ? __ldcs(s + 2) : f1;   // Y=255 in copy1 is never sampled
        __half h0 = __float2half_rn(f0);
        __half h1 = __float2half_rn(f1);
        __half h2 = __float2half_rn(f2);
        b0.h[c] = __halves2half2(h0, h1);
        b1.h[c] = __halves2half2(h1, h2);
    }

    uint4* d0 = reinterpret_cast<uint4*>(g_pack + (size_t)idx * 32);
    uint4* d1 = reinterpret_cast<uint4*>(g_pack + COPY_STRIDE + (size_t)idx * 32);
#pragma unroll
    for (int i = 0; i < 4; ++i) { d0[i] = b0.u[i]; d1[i] = b1.u[i]; }
}

// ---------------------------------------------------------------------------
// Sampling: FOUR threads per (point, plane); lane q owns channels 4q..4q+3.
// Each lane does 2x LDG.128 (rows xi, xi+1); each 16B piece carries its 4
// channels for BOTH y-corners (interleaved half2). 4 lanes of a pp cover one
// aligned 64B block -> 1 L1 wavefront per row per pp; 2 total (was 4).
// No shuffles: lane-exclusive channels, coalesced float4 store as before.
// ---------------------------------------------------------------------------
__global__ void __launch_bounds__(256) sample_k(const float* __restrict__ xyz,
                                                float* __restrict__ out, int nPP) {
    int g  = blockIdx.x * 256 + threadIdx.x;
    int pp = g >> 2;
    int q  = g & 3;
    if (pp >= nPP) return;
    int n  = pp / 3;
    int pl = pp - n * 3;

    float X = __ldg(xyz + 3 * n + 0);
    float Y = __ldg(xyz + 3 * n + 1);
    float Z = __ldg(xyz + 3 * n + 2);

    // pl 0: planes[0], (x, y); pl 1: planes[2], (y, z/0.05); pl 2: planes[1], (z/0.05, x)
    float c0, c1; int fp;
    if (pl == 0)      { c0 = X;         c1 = Y;         fp = 0; }
    else if (pl == 1) { c0 = Y;         c1 = Z / 0.05f; fp = 2; }
    else              { c0 = Z / 0.05f; c1 = X;         fp = 1; }

    float x = (c0 + 1.0f) * 255.5f;   // identical rounding to reference
    float y = (c1 + 1.0f) * 255.5f;

    float x0f = floorf(x), y0f = floorf(y);
    float fx = x - x0f;   // exact
    float fy = y - y0f;
    float gx = 1.0f - fx;
    float gy = 1.0f - fy;

    float wa = gx * gy;   // (x0, y0)
    float wb = fx * gy;   // (x1, y0)
    float wc = gx * fy;   // (x0, y1)
    float wd = fx * fy;   // (x1, y1)

    int xi = min(max((int)x0f, 0), RES - 2);
    int yi = min(max((int)y0f, 0), RES - 2);

    int copy = yi & 1;
    int Yi   = yi >> 1;   // for odd yi: (yi-1)/2; block rows = (yi, yi+1) in both cases

    // halves offset: [copy][fp][xi][Yi] blocks of 32 halves; lane piece +q*8
    int base = ((((copy * 3 + fp) << 9) + xi) * 256 + Yi) * 32 + q * 8;

    uint4 u0 = __ldg(reinterpret_cast<const uint4*>(g_pack + base));               // row xi
    uint4 u1 = __ldg(reinterpret_cast<const uint4*>(g_pack + base + ROW_STRIDE));  // row xi+1

    const __half2* h0 = reinterpret_cast<const __half2*>(&u0);
    const __half2* h1 = reinterpret_cast<const __half2*>(&u1);

    float4 r;
#define CHV(c, dst) {                                                   \
        float2 a = __half22float2(h0[c]);  /* (y0, y1) @ row xi   */    \
        float2 b = __half22float2(h1[c]);  /* (y0, y1) @ row xi+1 */    \
        dst = wa * a.x + wc * a.y + wb * b.x + wd * b.y; }
    CHV(0, r.x)
    CHV(1, r.y)
    CHV(2, r.z)
    CHV(3, r.w)
#undef CHV

    __stcs(reinterpret_cast<float4*>(out) + (size_t)pp * 4 + q, r);
}

extern "C" void kernel_launch(void* const* d_in, const int* in_sizes, int n_in,
                              void* d_out, int out_size) {
    const float* xyz = (const float*)d_in[0];   // (N, 3) float32
    const float* fm  = (const float*)d_in[1];   // (48, 512, 512) float32
    float* out = (float*)d_out;                 // (N, 48) float32
    int N = in_sizes[0] / 3;
    int nPP = N * 3;
    long long threads = (long long)nPP * 4;
    int blocks = (int)((threads + 255) / 256);

    pack_k<<<(3 * 512 * 256) / 256, 256>>>(fm);
    sample_k<<<blocks, 256>>>(xyz, out, nPP);
}